// round 1
// baseline (speedup 1.0000x reference)
#include <cuda_runtime.h>
#include <cuda_bf16.h>

#define N_NODE 1025
#define F3     96
#define KCONV  36864   // 64*64*9 active conv elements per filter
#define KLIN   4096    // 64*64
#define OUT_OC 0
#define OUT_OL 18874368          // 512*36864
#define OUT_OB 19922944          // + 256*4096

// ---------------- scratch (device globals; no allocations allowed) ----------
__device__ float g_encT[KCONV * 32];   // conv enc weights gathered+transposed [t][h]
__device__ float g_linT[KLIN * 32];    // lin  enc weights gathered+transposed [t][h]
__device__ float g_feats[N_NODE * F3];
__device__ float g_dinv[N_NODE];
__device__ float g_t1[N_NODE * F3];    // dinv-scaled feats@W1
__device__ float g_h[N_NODE * F3];     // relu(An @ t1)
__device__ float g_t2[N_NODE * F3];    // dinv-scaled h@W2
__device__ float g_x[N_NODE * F3];     // An @ t2

// active->padded index maps
__device__ __forceinline__ int conv_idx(int t) {
    int r = t / 9, s = t - r * 9;
    int a = r >> 6, b = r & 63;
    return a * 1152 + b * 9 + s;      // (a*128+b)*9 + s
}
__device__ __forceinline__ int lin_idx(int t) {
    return ((t >> 6) << 7) + (t & 63); // a*128 + b
}

// ---------------- 1. gather+transpose encoder weights -----------------------
// mode 0: conv (stride 147456 -> g_encT), mode 1: lin (stride 16384 -> g_linT)
__global__ void k_prep_T(const float* __restrict__ W, int mode) {
    __shared__ float sm[32][33];
    int t0 = blockIdx.x * 32;
    int tl = threadIdx.x & 31, h = threadIdx.x >> 5;
    int t = t0 + tl;
    int idx = (mode == 0) ? conv_idx(t) : lin_idx(t);
    int stride = (mode == 0) ? 147456 : 16384;
    sm[tl][h] = W[h * stride + idx];
    __syncthreads();
    int h2 = threadIdx.x & 31, tl2 = threadIdx.x >> 5;
    float* out = (mode == 0) ? g_encT : g_linT;
    out[(t0 + tl2) * 32 + h2] = sm[tl2][h2];
}

// ---------------- 2. init feats (row0 ones, enc biases, embeddings) ---------
__global__ void k_init(const float* __restrict__ ceb, const float* __restrict__ leb,
                       const float* __restrict__ emb, const int* __restrict__ prims) {
    int e = blockIdx.x * 256 + threadIdx.x;
    if (e >= N_NODE * F3) return;
    int row = e / F3, c = e - row * F3;
    float v;
    if (row == 0) v = 1.0f;
    else {
        int i = row - 1;
        if (c >= 64)      v = emb[prims[i] * 32 + (c - 64)];
        else {
            int h = c & 31;
            if (i < 512)      v = ceb[h];
            else if (i < 768) v = leb[h];
            else              v = 0.0f; // bias-enc rows fully written later
        }
    }
    g_feats[e] = v;
}

// ---------------- 3. dinv = rsqrt(rowsum(adj)+1) -----------------------------
__global__ void k_dinv(const int* __restrict__ adj) {
    __shared__ int red[256];
    int i = blockIdx.x;
    int s = 0;
    for (int j = threadIdx.x; j < N_NODE; j += 256) s += adj[i * N_NODE + j];
    red[threadIdx.x] = s;
    __syncthreads();
    for (int off = 128; off > 0; off >>= 1) {
        if (threadIdx.x < off) red[threadIdx.x] += red[threadIdx.x + off];
        __syncthreads();
    }
    if (threadIdx.x == 0) g_dinv[i] = rsqrtf((float)(red[0] + 1));
}

// ---------------- 4. encoder GEMM: enc = A(M,K) @ Bt(K,32), K-split ---------
// grid (M/64, K/1024), block 256.  Adds into g_feats at [row][h] and [row][32+h].
__global__ __launch_bounds__(256) void k_enc_gemm(const float* __restrict__ A,
                                                  int K, int mode, int featrow0) {
    __shared__ float As[64 * 32];
    __shared__ float Bs[32 * 32];
    const float* __restrict__ Bt = (mode == 0) ? g_encT : g_linT;
    int h = threadIdx.x & 31, grp = threadIdx.x >> 5;
    int rowb = blockIdx.x * 64;
    int kbase = blockIdx.y * 1024;
    float acc[8] = {0, 0, 0, 0, 0, 0, 0, 0};
    for (int kt = 0; kt < 1024; kt += 32) {
        int k0 = kbase + kt;
#pragma unroll
        for (int jj = 0; jj < 8; jj++) {
            int e = threadIdx.x + jj * 256;
            int r = e >> 5, kk = e & 31;
            As[e] = A[(rowb + r) * K + k0 + kk];
        }
#pragma unroll
        for (int jj = 0; jj < 4; jj++) {
            int e = threadIdx.x + jj * 256;
            Bs[e] = Bt[k0 * 32 + e];
        }
        __syncthreads();
#pragma unroll
        for (int kk = 0; kk < 32; kk += 4) {
            float b0 = Bs[(kk + 0) * 32 + h], b1 = Bs[(kk + 1) * 32 + h];
            float b2 = Bs[(kk + 2) * 32 + h], b3 = Bs[(kk + 3) * 32 + h];
#pragma unroll
            for (int r8 = 0; r8 < 8; r8++) {
                const float4 a = *(const float4*)&As[(grp * 8 + r8) * 32 + kk];
                acc[r8] += a.x * b0 + a.y * b1 + a.z * b2 + a.w * b3;
            }
        }
        __syncthreads();
    }
#pragma unroll
    for (int r8 = 0; r8 < 8; r8++) {
        int row = featrow0 + rowb + grp * 8 + r8;
        atomicAdd(&g_feats[row * F3 + h], acc[r8]);
        atomicAdd(&g_feats[row * F3 + 32 + h], acc[r8]);
    }
}

// ---------------- 5. bias encoder (tiny) ------------------------------------
// grid 32, block 256 = (32 h, 8 i)
__global__ void k_bias_enc(const float* __restrict__ bw, const float* __restrict__ Wb,
                           const float* __restrict__ bb) {
    __shared__ float sW[32 * 65];
    __shared__ float sB[8 * 64];
    int tid = threadIdx.x;
    for (int e = tid; e < 32 * 64; e += 256) {
        int hh = e >> 6, t = e & 63;
        sW[hh * 65 + t] = Wb[hh * 128 + t];
    }
    int ibase = blockIdx.x * 8;
    for (int e = tid; e < 8 * 64; e += 256) sB[e] = bw[ibase * 64 + e];
    __syncthreads();
    int h = tid & 31, ii = tid >> 5;
    float acc = 0.0f;
#pragma unroll
    for (int t = 0; t < 64; t++) acc += sB[ii * 64 + t] * sW[h * 65 + t];
    acc += bb[h];
    int row = 769 + ibase + ii;
    g_feats[row * F3 + h] = acc;
    g_feats[row * F3 + 32 + h] = acc;
}

// ---------------- 6. small dense GEMM: out[l] = dinv[l]*(in[l] @ W) ---------
// grid 129, block 96.  sel 0: feats->t1 (W1); sel 1: h->t2 (W2)
__global__ void k_gcn_mm(const float* __restrict__ W, int sel) {
    __shared__ float ws[96 * 96];
    __shared__ float fr[8 * 96];
    const float* __restrict__ in = sel ? g_h : g_feats;
    float* __restrict__ out = sel ? g_t2 : g_t1;
    int j = threadIdx.x;
    for (int e = j; e < 96 * 96; e += 96) ws[e] = W[e];
    int rb = blockIdx.x * 8;
#pragma unroll
    for (int rr = 0; rr < 8; rr++) {
        int row = rb + rr;
        fr[rr * 96 + j] = (row < N_NODE) ? in[row * 96 + j] : 0.0f;
    }
    __syncthreads();
#pragma unroll
    for (int rr = 0; rr < 8; rr++) {
        int row = rb + rr;
        if (row >= N_NODE) break;
        float acc = 0.0f;
#pragma unroll 8
        for (int k = 0; k < 96; k++) acc += fr[rr * 96 + k] * ws[k * 96 + j];
        out[row * 96 + j] = g_dinv[row] * acc;
    }
}

// ---------------- 7. SpMM vs dense 0/1 adjacency ----------------------------
// grid 129, block (96,4).  sel 0: t1 -> h (relu); sel 1: t2 -> x
__global__ void k_spmm(const int* __restrict__ adj, int sel) {
    __shared__ float sT[64 * 96];
    __shared__ float sA[8 * 64];
    const float* __restrict__ ts = sel ? g_t2 : g_t1;
    float* __restrict__ out = sel ? g_x : g_h;
    int j = threadIdx.x, ry = threadIdx.y;
    int tid = ry * 96 + j;
    int rb = blockIdx.x * 8;
    float acc0 = 0.0f, acc1 = 0.0f;
    for (int lb = 0; lb < N_NODE; lb += 64) {
        for (int e = tid; e < 64 * 96; e += 384) {
            int l = e / 96, c = e - l * 96;
            int lg = lb + l;
            sT[e] = (lg < N_NODE) ? ts[lg * 96 + c] : 0.0f;
        }
        for (int e = tid; e < 8 * 64; e += 384) {
            int r = e >> 6, l = e & 63;
            int rg = rb + r, lg = lb + l;
            sA[e] = (rg < N_NODE && lg < N_NODE) ? (float)adj[rg * N_NODE + lg] : 0.0f;
        }
        __syncthreads();
#pragma unroll
        for (int l = 0; l < 64; l += 4) {
            float4 a0 = *(const float4*)&sA[ry * 64 + l];
            float4 a1 = *(const float4*)&sA[(ry + 4) * 64 + l];
            float t0 = sT[(l + 0) * 96 + j], t1 = sT[(l + 1) * 96 + j];
            float t2 = sT[(l + 2) * 96 + j], t3 = sT[(l + 3) * 96 + j];
            acc0 += a0.x * t0 + a0.y * t1 + a0.z * t2 + a0.w * t3;
            acc1 += a1.x * t0 + a1.y * t1 + a1.z * t2 + a1.w * t3;
        }
        __syncthreads();
    }
    int r0 = rb + ry, r1 = rb + ry + 4;
    if (r0 < N_NODE) {
        float v = (acc0 + ts[r0 * 96 + j]) * g_dinv[r0];
        if (!sel) v = fmaxf(v, 0.0f);
        out[r0 * 96 + j] = v;
    }
    if (r1 < N_NODE) {
        float v = (acc1 + ts[r1 * 96 + j]) * g_dinv[r1];
        if (!sel) v = fmaxf(v, 0.0f);
        out[r1 * 96 + j] = v;
    }
}

// ---------------- 8. decoder GEMM: out[i][t] = x[xrow0+i] . Wd[idx(t)] + b --
// grid (Ntot/64, M/64), block 256 (16x16 threads, 4x4 micro-tile)
__global__ __launch_bounds__(256) void k_dec(const float* __restrict__ Wd,
                                             const float* __restrict__ bd,
                                             float* __restrict__ out,
                                             int Ntot, int xrow0, int mode, int outoff) {
    __shared__ float Xs[48 * 68];
    __shared__ float Ws[48 * 68];
    __shared__ float bias_s[64];
    int tid = threadIdx.x;
    int tx = tid & 15, ty = tid >> 4;
    int tbase = blockIdx.x * 64;
    int ibase = blockIdx.y * 64;
    if (tid < 64) {
        int tg = tbase + tid;
        int id = (mode == 0) ? conv_idx(tg) : lin_idx(tg);
        bias_s[tid] = bd[id];
    }
    float acc[4][4] = {};
    for (int kc = 0; kc < 96; kc += 48) {
        __syncthreads();
        for (int e = tid; e < 64 * 48; e += 256) {
            int r = e / 48, k = e - r * 48;
            Xs[k * 68 + r] = g_x[(xrow0 + ibase + r) * 96 + kc + k];
        }
        for (int e = tid; e < 64 * 48; e += 256) {
            int c = e / 48, k = e - c * 48;
            int tg = tbase + c;
            int id = (mode == 0) ? conv_idx(tg) : lin_idx(tg);
            Ws[k * 68 + c] = Wd[id * 96 + kc + k];
        }
        __syncthreads();
#pragma unroll
        for (int k = 0; k < 48; k++) {
            float4 a = *(const float4*)&Xs[k * 68 + ty * 4];
            float4 b = *(const float4*)&Ws[k * 68 + tx * 4];
            acc[0][0] += a.x * b.x; acc[0][1] += a.x * b.y; acc[0][2] += a.x * b.z; acc[0][3] += a.x * b.w;
            acc[1][0] += a.y * b.x; acc[1][1] += a.y * b.y; acc[1][2] += a.y * b.z; acc[1][3] += a.y * b.w;
            acc[2][0] += a.z * b.x; acc[2][1] += a.z * b.y; acc[2][2] += a.z * b.z; acc[2][3] += a.z * b.w;
            acc[3][0] += a.w * b.x; acc[3][1] += a.w * b.y; acc[3][2] += a.w * b.z; acc[3][3] += a.w * b.w;
        }
    }
#pragma unroll
    for (int ri = 0; ri < 4; ri++) {
        int r = ibase + ty * 4 + ri;
        float4 v;
        v.x = acc[ri][0] + bias_s[tx * 4 + 0];
        v.y = acc[ri][1] + bias_s[tx * 4 + 1];
        v.z = acc[ri][2] + bias_s[tx * 4 + 2];
        v.w = acc[ri][3] + bias_s[tx * 4 + 3];
        *(float4*)&out[outoff + r * Ntot + tbase + tx * 4] = v;
    }
}

// ---------------- 9. bias decoder (tiny) ------------------------------------
// grid 256, block 96
__global__ void k_dec_bias(const float* __restrict__ Wd, const float* __restrict__ bd,
                           float* __restrict__ out) {
    __shared__ float xr[96];
    int i = blockIdx.x;
    xr[threadIdx.x] = g_x[(769 + i) * 96 + threadIdx.x];
    __syncthreads();
    int t = threadIdx.x;
    if (t < 64) {
        float acc = 0.0f;
#pragma unroll 8
        for (int k = 0; k < 96; k++) acc += xr[k] * Wd[t * 96 + k];
        out[OUT_OB + i * 64 + t] = acc + bd[t];
    }
}

// ---------------- launch -----------------------------------------------------
extern "C" void kernel_launch(void* const* d_in, const int* in_sizes, int n_in,
                              void* d_out, int out_size) {
    const float* conv_w     = (const float*)d_in[0];
    const float* lin_w      = (const float*)d_in[1];
    const float* bias_w     = (const float*)d_in[2];
    const float* conv_enc_w = (const float*)d_in[3];
    const float* conv_enc_b = (const float*)d_in[4];
    const float* lin_enc_w  = (const float*)d_in[5];
    const float* lin_enc_b  = (const float*)d_in[6];
    const float* bias_enc_w = (const float*)d_in[7];
    const float* bias_enc_b = (const float*)d_in[8];
    const float* gcn_w1     = (const float*)d_in[9];
    const float* gcn_w2     = (const float*)d_in[10];
    const float* conv_dec_w = (const float*)d_in[11];
    const float* conv_dec_b = (const float*)d_in[12];
    const float* lin_dec_w  = (const float*)d_in[13];
    const float* lin_dec_b  = (const float*)d_in[14];
    const float* bias_dec_w = (const float*)d_in[15];
    const float* bias_dec_b = (const float*)d_in[16];
    const float* embed_tab  = (const float*)d_in[17];
    const int*   adj        = (const int*)d_in[18];
    const int*   node_prims = (const int*)d_in[19];
    float* out = (float*)d_out;

    (void)in_sizes; (void)n_in; (void)out_size;

    // weight gathers (independent of inputs' values per call, but cheap; keep in graph)
    k_prep_T<<<KCONV / 32, 1024>>>(conv_enc_w, 0);
    k_prep_T<<<KLIN / 32, 1024>>>(lin_enc_w, 1);

    k_init<<<(N_NODE * F3 + 255) / 256, 256>>>(conv_enc_b, lin_enc_b, embed_tab, node_prims);
    k_dinv<<<N_NODE, 256>>>(adj);

    k_enc_gemm<<<dim3(8, 36), 256>>>(conv_w, KCONV, 0, 1);
    k_enc_gemm<<<dim3(4, 4), 256>>>(lin_w, KLIN, 1, 513);
    k_bias_enc<<<32, 256>>>(bias_w, bias_enc_w, bias_enc_b);

    k_gcn_mm<<<129, 96>>>(gcn_w1, 0);
    k_spmm<<<129, dim3(96, 4)>>>(adj, 0);
    k_gcn_mm<<<129, 96>>>(gcn_w2, 1);
    k_spmm<<<129, dim3(96, 4)>>>(adj, 1);

    k_dec<<<dim3(576, 8), 256>>>(conv_dec_w, conv_dec_b, out, 36864, 1, 0, OUT_OC);
    k_dec<<<dim3(64, 4), 256>>>(lin_dec_w, lin_dec_b, out, 4096, 513, 1, OUT_OL);
    k_dec_bias<<<256, 96>>>(bias_dec_w, bias_dec_b, out);
}

// round 2
// speedup vs baseline: 1.0641x; 1.0641x over previous
#include <cuda_runtime.h>
#include <cuda_bf16.h>

#define N_NODE 1025
#define F3     96
#define KCONV  36864   // 64*64*9 active conv elements per filter
#define KLIN   4096    // 64*64
#define OUT_OC 0
#define OUT_OL 18874368          // 512*36864
#define OUT_OB 19922944          // + 256*4096

// ---------------- scratch (device globals; no allocations allowed) ----------
__device__ float g_encT[KCONV * 32];   // conv enc weights gathered+transposed [t][h]
__device__ float g_linT[KLIN * 32];    // lin  enc weights gathered+transposed [t][h]
__device__ float g_feats[N_NODE * F3];
__device__ float g_dinv[N_NODE];
__device__ float g_t1[N_NODE * F3];    // dinv-scaled feats@W1
__device__ float g_h[N_NODE * F3];     // relu(An @ t1)
__device__ float g_t2[N_NODE * F3];    // dinv-scaled h@W2
__device__ float g_x[N_NODE * F3];     // An @ t2

// active->padded index maps
__device__ __forceinline__ int conv_idx(int t) {
    int r = t / 9, s = t - r * 9;
    int a = r >> 6, b = r & 63;
    return a * 1152 + b * 9 + s;      // (a*128+b)*9 + s
}
__device__ __forceinline__ int lin_idx(int t) {
    return ((t >> 6) << 7) + (t & 63); // a*128 + b
}

__device__ __forceinline__ unsigned f2tf32(float f) {
    unsigned u;
    asm("cvt.rna.tf32.f32 %0, %1;" : "=r"(u) : "f"(f));
    return u;
}

__device__ __forceinline__ void mma_tf32(float c[4], const unsigned a[4], const unsigned b[2]) {
    asm volatile("mma.sync.aligned.m16n8k8.row.col.f32.tf32.tf32.f32 "
                 "{%0,%1,%2,%3}, {%4,%5,%6,%7}, {%8,%9}, {%0,%1,%2,%3};"
                 : "+f"(c[0]), "+f"(c[1]), "+f"(c[2]), "+f"(c[3])
                 : "r"(a[0]), "r"(a[1]), "r"(a[2]), "r"(a[3]),
                   "r"(b[0]), "r"(b[1]));
}

// ---------------- 1. gather+transpose encoder weights -----------------------
__global__ void k_prep_T(const float* __restrict__ W, int mode) {
    __shared__ float sm[32][33];
    int t0 = blockIdx.x * 32;
    int tl = threadIdx.x & 31, h = threadIdx.x >> 5;
    int t = t0 + tl;
    int idx = (mode == 0) ? conv_idx(t) : lin_idx(t);
    int stride = (mode == 0) ? 147456 : 16384;
    sm[tl][h] = W[h * stride + idx];
    __syncthreads();
    int h2 = threadIdx.x & 31, tl2 = threadIdx.x >> 5;
    float* out = (mode == 0) ? g_encT : g_linT;
    out[(t0 + tl2) * 32 + h2] = sm[tl2][h2];
}

// ---------------- 2. init feats ---------------------------------------------
__global__ void k_init(const float* __restrict__ ceb, const float* __restrict__ leb,
                       const float* __restrict__ emb, const int* __restrict__ prims) {
    int e = blockIdx.x * 256 + threadIdx.x;
    if (e >= N_NODE * F3) return;
    int row = e / F3, c = e - row * F3;
    float v;
    if (row == 0) v = 1.0f;
    else {
        int i = row - 1;
        if (c >= 64)      v = emb[prims[i] * 32 + (c - 64)];
        else {
            int h = c & 31;
            if (i < 512)      v = ceb[h];
            else if (i < 768) v = leb[h];
            else              v = 0.0f;
        }
    }
    g_feats[e] = v;
}

// ---------------- 3. dinv ----------------------------------------------------
__global__ void k_dinv(const int* __restrict__ adj) {
    __shared__ int red[256];
    int i = blockIdx.x;
    int s = 0;
    for (int j = threadIdx.x; j < N_NODE; j += 256) s += adj[i * N_NODE + j];
    red[threadIdx.x] = s;
    __syncthreads();
    for (int off = 128; off > 0; off >>= 1) {
        if (threadIdx.x < off) red[threadIdx.x] += red[threadIdx.x + off];
        __syncthreads();
    }
    if (threadIdx.x == 0) g_dinv[i] = rsqrtf((float)(red[0] + 1));
}

// ---------------- 4. encoder GEMM (fp32 FFMA, K-split) ----------------------
__global__ __launch_bounds__(256) void k_enc_gemm(const float* __restrict__ A,
                                                  int K, int mode, int featrow0) {
    __shared__ float As[64 * 32];
    __shared__ float Bs[32 * 32];
    const float* __restrict__ Bt = (mode == 0) ? g_encT : g_linT;
    int h = threadIdx.x & 31, grp = threadIdx.x >> 5;
    int rowb = blockIdx.x * 64;
    int kbase = blockIdx.y * 1024;
    float acc[8] = {0, 0, 0, 0, 0, 0, 0, 0};
    for (int kt = 0; kt < 1024; kt += 32) {
        int k0 = kbase + kt;
#pragma unroll
        for (int jj = 0; jj < 8; jj++) {
            int e = threadIdx.x + jj * 256;
            int r = e >> 5, kk = e & 31;
            As[e] = A[(rowb + r) * K + k0 + kk];
        }
#pragma unroll
        for (int jj = 0; jj < 4; jj++) {
            int e = threadIdx.x + jj * 256;
            Bs[e] = Bt[k0 * 32 + e];
        }
        __syncthreads();
#pragma unroll
        for (int kk = 0; kk < 32; kk += 4) {
            float b0 = Bs[(kk + 0) * 32 + h], b1 = Bs[(kk + 1) * 32 + h];
            float b2 = Bs[(kk + 2) * 32 + h], b3 = Bs[(kk + 3) * 32 + h];
#pragma unroll
            for (int r8 = 0; r8 < 8; r8++) {
                const float4 a = *(const float4*)&As[(grp * 8 + r8) * 32 + kk];
                acc[r8] += a.x * b0 + a.y * b1 + a.z * b2 + a.w * b3;
            }
        }
        __syncthreads();
    }
#pragma unroll
    for (int r8 = 0; r8 < 8; r8++) {
        int row = featrow0 + rowb + grp * 8 + r8;
        atomicAdd(&g_feats[row * F3 + h], acc[r8]);
        atomicAdd(&g_feats[row * F3 + 32 + h], acc[r8]);
    }
}

// ---------------- 5. bias encoder -------------------------------------------
__global__ void k_bias_enc(const float* __restrict__ bw, const float* __restrict__ Wb,
                           const float* __restrict__ bb) {
    __shared__ float sW[32 * 65];
    __shared__ float sB[8 * 64];
    int tid = threadIdx.x;
    for (int e = tid; e < 32 * 64; e += 256) {
        int hh = e >> 6, t = e & 63;
        sW[hh * 65 + t] = Wb[hh * 128 + t];
    }
    int ibase = blockIdx.x * 8;
    for (int e = tid; e < 8 * 64; e += 256) sB[e] = bw[ibase * 64 + e];
    __syncthreads();
    int h = tid & 31, ii = tid >> 5;
    float acc = 0.0f;
#pragma unroll
    for (int t = 0; t < 64; t++) acc += sB[ii * 64 + t] * sW[h * 65 + t];
    acc += bb[h];
    int row = 769 + ibase + ii;
    g_feats[row * F3 + h] = acc;
    g_feats[row * F3 + 32 + h] = acc;
}

// ---------------- 6. GCN dense GEMM -----------------------------------------
__global__ void k_gcn_mm(const float* __restrict__ W, int sel) {
    __shared__ float ws[96 * 96];
    __shared__ float fr[8 * 96];
    const float* __restrict__ in = sel ? g_h : g_feats;
    float* __restrict__ out = sel ? g_t2 : g_t1;
    int j = threadIdx.x;
    for (int e = j; e < 96 * 96; e += 96) ws[e] = W[e];
    int rb = blockIdx.x * 8;
#pragma unroll
    for (int rr = 0; rr < 8; rr++) {
        int row = rb + rr;
        fr[rr * 96 + j] = (row < N_NODE) ? in[row * 96 + j] : 0.0f;
    }
    __syncthreads();
#pragma unroll
    for (int rr = 0; rr < 8; rr++) {
        int row = rb + rr;
        if (row >= N_NODE) break;
        float acc = 0.0f;
#pragma unroll 8
        for (int k = 0; k < 96; k++) acc += fr[rr * 96 + k] * ws[k * 96 + j];
        out[row * 96 + j] = g_dinv[row] * acc;
    }
}

// ---------------- 7. SpMM ----------------------------------------------------
__global__ void k_spmm(const int* __restrict__ adj, int sel) {
    __shared__ float sT[64 * 96];
    __shared__ float sA[8 * 64];
    const float* __restrict__ ts = sel ? g_t2 : g_t1;
    float* __restrict__ out = sel ? g_x : g_h;
    int j = threadIdx.x, ry = threadIdx.y;
    int tid = ry * 96 + j;
    int rb = blockIdx.x * 8;
    float acc0 = 0.0f, acc1 = 0.0f;
    for (int lb = 0; lb < N_NODE; lb += 64) {
        for (int e = tid; e < 64 * 96; e += 384) {
            int l = e / 96, c = e - l * 96;
            int lg = lb + l;
            sT[e] = (lg < N_NODE) ? ts[lg * 96 + c] : 0.0f;
        }
        for (int e = tid; e < 8 * 64; e += 384) {
            int r = e >> 6, l = e & 63;
            int rg = rb + r, lg = lb + l;
            sA[e] = (rg < N_NODE && lg < N_NODE) ? (float)adj[rg * N_NODE + lg] : 0.0f;
        }
        __syncthreads();
#pragma unroll
        for (int l = 0; l < 64; l += 4) {
            float4 a0 = *(const float4*)&sA[ry * 64 + l];
            float4 a1 = *(const float4*)&sA[(ry + 4) * 64 + l];
            float t0 = sT[(l + 0) * 96 + j], t1 = sT[(l + 1) * 96 + j];
            float t2 = sT[(l + 2) * 96 + j], t3 = sT[(l + 3) * 96 + j];
            acc0 += a0.x * t0 + a0.y * t1 + a0.z * t2 + a0.w * t3;
            acc1 += a1.x * t0 + a1.y * t1 + a1.z * t2 + a1.w * t3;
        }
        __syncthreads();
    }
    int r0 = rb + ry, r1 = rb + ry + 4;
    if (r0 < N_NODE) {
        float v = (acc0 + ts[r0 * 96 + j]) * g_dinv[r0];
        if (!sel) v = fmaxf(v, 0.0f);
        out[r0 * 96 + j] = v;
    }
    if (r1 < N_NODE) {
        float v = (acc1 + ts[r1 * 96 + j]) * g_dinv[r1];
        if (!sel) v = fmaxf(v, 0.0f);
        out[r1 * 96 + j] = v;
    }
}

// ---------------- 8. decoder GEMM, tf32 tensor cores ------------------------
// C[i][t] = x[xrow0+i][:] . Wd[idx(t)][:] + bd[idx(t)]
// Block tile 64(M) x 128(N), K chunks of 48. 256 threads = 8 warps (2M x 4N).
// Warp tile 32x32 -> 2x4 m16n8 mma tiles per k8-step.
// Smem strides 73 / 137 (odd) -> conflict-free transposed stores.
__global__ __launch_bounds__(256) void k_dec_tf32(const float* __restrict__ Wd,
                                                  const float* __restrict__ bd,
                                                  float* __restrict__ out,
                                                  int Ntot, int xrow0, int mode,
                                                  long long outoff) {
    __shared__ unsigned Xs[48 * 73];    // [k][m], stride 73
    __shared__ unsigned Ws[48 * 137];   // [k][n], stride 137
    __shared__ float bias_s[128];

    int tid = threadIdx.x;
    int warp = tid >> 5, lane = tid & 31;
    int g = lane >> 2, tg = lane & 3;
    int wm0 = (warp >> 2) * 32;         // warp M offset (0 or 32)
    int wn0 = (warp & 3) * 32;          // warp N offset (0,32,64,96)
    int tbase = blockIdx.x * 128;
    int ibase = blockIdx.y * 64;

    if (tid < 128) {
        int tglob = tbase + tid;
        int id = (mode == 0) ? conv_idx(tglob) : lin_idx(tglob);
        bias_s[tid] = bd[id];
    }

    float acc[2][4][4];
#pragma unroll
    for (int mi = 0; mi < 2; mi++)
#pragma unroll
        for (int ni = 0; ni < 4; ni++)
#pragma unroll
            for (int q = 0; q < 4; q++) acc[mi][ni][q] = 0.0f;

    for (int kc = 0; kc < 96; kc += 48) {
        __syncthreads();
        // stage X: 64 rows x 48 k -> Xs[k][m]
        for (int e = tid; e < 64 * 48; e += 256) {
            int m = e / 48, k = e - m * 48;
            float v = g_x[(xrow0 + ibase + m) * 96 + kc + k];
            Xs[k * 73 + m] = f2tf32(v);
        }
        // stage W: 128 cols x 48 k -> Ws[k][n]
        for (int e = tid; e < 128 * 48; e += 256) {
            int n = e / 48, k = e - n * 48;
            int tglob = tbase + n;
            int id = (mode == 0) ? conv_idx(tglob) : lin_idx(tglob);
            float v = Wd[id * 96 + kc + k];
            Ws[k * 137 + n] = f2tf32(v);
        }
        __syncthreads();

#pragma unroll
        for (int ks = 0; ks < 6; ks++) {
            int k0 = ks * 8;
            unsigned a[2][4], b[4][2];
#pragma unroll
            for (int mi = 0; mi < 2; mi++) {
                int m = wm0 + mi * 16 + g;
                a[mi][0] = Xs[(k0 + tg) * 73 + m];
                a[mi][1] = Xs[(k0 + tg) * 73 + m + 8];
                a[mi][2] = Xs[(k0 + tg + 4) * 73 + m];
                a[mi][3] = Xs[(k0 + tg + 4) * 73 + m + 8];
            }
#pragma unroll
            for (int ni = 0; ni < 4; ni++) {
                int n = wn0 + ni * 8 + g;
                b[ni][0] = Ws[(k0 + tg) * 137 + n];
                b[ni][1] = Ws[(k0 + tg + 4) * 137 + n];
            }
#pragma unroll
            for (int mi = 0; mi < 2; mi++)
#pragma unroll
                for (int ni = 0; ni < 4; ni++)
                    mma_tf32(acc[mi][ni], a[mi], b[ni]);
        }
    }

    // epilogue: c0 (g, 2tg), c1 (g, 2tg+1), c2 (g+8, 2tg), c3 (g+8, 2tg+1)
#pragma unroll
    for (int mi = 0; mi < 2; mi++) {
        int row0 = ibase + wm0 + mi * 16 + g;
#pragma unroll
        for (int ni = 0; ni < 4; ni++) {
            int ncol = wn0 + ni * 8 + 2 * tg;
            int col = tbase + ncol;
            float bx = bias_s[ncol], by = bias_s[ncol + 1];
            float2 v0 = make_float2(acc[mi][ni][0] + bx, acc[mi][ni][1] + by);
            float2 v1 = make_float2(acc[mi][ni][2] + bx, acc[mi][ni][3] + by);
            *(float2*)&out[outoff + (long long)row0 * Ntot + col] = v0;
            *(float2*)&out[outoff + (long long)(row0 + 8) * Ntot + col] = v1;
        }
    }
}

// ---------------- 9. bias decoder (tiny) ------------------------------------
__global__ void k_dec_bias(const float* __restrict__ Wd, const float* __restrict__ bd,
                           float* __restrict__ out) {
    __shared__ float xr[96];
    int i = blockIdx.x;
    xr[threadIdx.x] = g_x[(769 + i) * 96 + threadIdx.x];
    __syncthreads();
    int t = threadIdx.x;
    if (t < 64) {
        float acc = 0.0f;
#pragma unroll 8
        for (int k = 0; k < 96; k++) acc += xr[k] * Wd[t * 96 + k];
        out[OUT_OB + i * 64 + t] = acc + bd[t];
    }
}

// ---------------- launch -----------------------------------------------------
extern "C" void kernel_launch(void* const* d_in, const int* in_sizes, int n_in,
                              void* d_out, int out_size) {
    const float* conv_w     = (const float*)d_in[0];
    const float* lin_w      = (const float*)d_in[1];
    const float* bias_w     = (const float*)d_in[2];
    const float* conv_enc_w = (const float*)d_in[3];
    const float* conv_enc_b = (const float*)d_in[4];
    const float* lin_enc_w  = (const float*)d_in[5];
    const float* lin_enc_b  = (const float*)d_in[6];
    const float* bias_enc_w = (const float*)d_in[7];
    const float* bias_enc_b = (const float*)d_in[8];
    const float* gcn_w1     = (const float*)d_in[9];
    const float* gcn_w2     = (const float*)d_in[10];
    const float* conv_dec_w = (const float*)d_in[11];
    const float* conv_dec_b = (const float*)d_in[12];
    const float* lin_dec_w  = (const float*)d_in[13];
    const float* lin_dec_b  = (const float*)d_in[14];
    const float* bias_dec_w = (const float*)d_in[15];
    const float* bias_dec_b = (const float*)d_in[16];
    const float* embed_tab  = (const float*)d_in[17];
    const int*   adj        = (const int*)d_in[18];
    const int*   node_prims = (const int*)d_in[19];
    float* out = (float*)d_out;

    (void)in_sizes; (void)n_in; (void)out_size;

    k_prep_T<<<KCONV / 32, 1024>>>(conv_enc_w, 0);
    k_prep_T<<<KLIN / 32, 1024>>>(lin_enc_w, 1);

    k_init<<<(N_NODE * F3 + 255) / 256, 256>>>(conv_enc_b, lin_enc_b, embed_tab, node_prims);
    k_dinv<<<N_NODE, 256>>>(adj);

    k_enc_gemm<<<dim3(8, 36), 256>>>(conv_w, KCONV, 0, 1);
    k_enc_gemm<<<dim3(4, 4), 256>>>(lin_w, KLIN, 1, 513);
    k_bias_enc<<<32, 256>>>(bias_w, bias_enc_w, bias_enc_b);

    k_gcn_mm<<<129, 96>>>(gcn_w1, 0);
    k_spmm<<<129, dim3(96, 4)>>>(adj, 0);
    k_gcn_mm<<<129, 96>>>(gcn_w2, 1);
    k_spmm<<<129, dim3(96, 4)>>>(adj, 1);

    k_dec_tf32<<<dim3(288, 8), 256>>>(conv_dec_w, conv_dec_b, out, 36864, 1, 0, (long long)OUT_OC);
    k_dec_tf32<<<dim3(32, 4), 256>>>(lin_dec_w, lin_dec_b, out, 4096, 513, 1, (long long)OUT_OL);
    k_dec_bias<<<256, 96>>>(bias_dec_w, bias_dec_b, out);
}